// round 2
// baseline (speedup 1.0000x reference)
#include <cuda_runtime.h>

// Precomputed broadcast row: row[c] = sum_d v[d]*Wo[d,c] + bo[c]
__device__ float g_row[256];

// Kernel 1: one block, 256 threads. Computes v (256 vals) then row (256 vals).
// Derivation: layer_norm over the size-1 kv feature axis gives exactly ln_k_b
// (mu=x, var=0 -> (x-mu)=0), so k and v are identical across all L positions;
// softmax over identical scores is uniform 1/L; o = mean(v) = v for every query.
// Hence out = msa + (v @ Wo + bo) broadcast over all 16384 rows.
__global__ void compute_row_kernel(const float* __restrict__ ln_k_b,
                                   const float* __restrict__ Wv,   // [1,256]
                                   const float* __restrict__ bv,   // [256]
                                   const float* __restrict__ Wo,   // [256,256]
                                   const float* __restrict__ bo)   // [256]
{
    __shared__ float v[256];
    int t = threadIdx.x;
    float kb = ln_k_b[0];
    v[t] = fmaf(kb, Wv[t], bv[t]);
    __syncthreads();

    // 8 independent partial sums to break the serial FMA dependency chain.
    float acc0 = 0.f, acc1 = 0.f, acc2 = 0.f, acc3 = 0.f;
    float acc4 = 0.f, acc5 = 0.f, acc6 = 0.f, acc7 = 0.f;
    #pragma unroll
    for (int d = 0; d < 256; d += 8) {
        acc0 = fmaf(v[d + 0], Wo[(d + 0) * 256 + t], acc0);
        acc1 = fmaf(v[d + 1], Wo[(d + 1) * 256 + t], acc1);
        acc2 = fmaf(v[d + 2], Wo[(d + 2) * 256 + t], acc2);
        acc3 = fmaf(v[d + 3], Wo[(d + 3) * 256 + t], acc3);
        acc4 = fmaf(v[d + 4], Wo[(d + 4) * 256 + t], acc4);
        acc5 = fmaf(v[d + 5], Wo[(d + 5) * 256 + t], acc5);
        acc6 = fmaf(v[d + 6], Wo[(d + 6) * 256 + t], acc6);
        acc7 = fmaf(v[d + 7], Wo[(d + 7) * 256 + t], acc7);
    }
    g_row[t] = bo[t] + (((acc0 + acc1) + (acc2 + acc3)) +
                        ((acc4 + acc5) + (acc6 + acc7)));
}

// Kernel 2: out = msa + broadcast(row). Pure HBM stream, float4 vectorized,
// grid-stride for robustness.
__global__ void add_row_kernel(const float4* __restrict__ msa4,
                               float4* __restrict__ out4,
                               int n4)
{
    __shared__ float4 row4[64];  // 256 floats = 64 float4
    int t = threadIdx.x;
    if (t < 64) {
        const float4* gr = reinterpret_cast<const float4*>(g_row);
        row4[t] = gr[t];
    }
    __syncthreads();

    // blockDim.x == 256 (multiple of 64), and grid stride is a multiple of 256,
    // so (i % 64) == (t % 64) for every iteration: row index is loop-invariant.
    float4 r = row4[t & 63];
    for (int i = blockIdx.x * blockDim.x + t; i < n4;
         i += gridDim.x * blockDim.x) {
        float4 m = msa4[i];
        float4 o;
        o.x = m.x + r.x;
        o.y = m.y + r.y;
        o.z = m.z + r.z;
        o.w = m.w + r.w;
        out4[i] = o;
    }
}

extern "C" void kernel_launch(void* const* d_in, const int* in_sizes, int n_in,
                              void* d_out, int out_size)
{
    // metadata order: 0 msa, 1 saxs, 2 ln_q_w, 3 ln_q_b, 4 ln_k_w, 5 ln_k_b,
    //                 6 Wq, 7 bq, 8 Wk, 9 bk, 10 Wv, 11 bv, 12 Wo, 13 bo
    const float* msa    = (const float*)d_in[0];
    const float* ln_k_b = (const float*)d_in[5];
    const float* Wv     = (const float*)d_in[10];
    const float* bv     = (const float*)d_in[11];
    const float* Wo     = (const float*)d_in[12];
    const float* bo     = (const float*)d_in[13];
    float* out = (float*)d_out;

    compute_row_kernel<<<1, 256>>>(ln_k_b, Wv, bv, Wo, bo);

    int n4 = out_size / 4;  // 4,194,304 floats -> 1,048,576 float4
    int threads = 256;
    int blocks = (n4 + threads - 1) / threads;  // one element per thread
    add_row_kernel<<<blocks, threads>>>((const float4*)msa, (float4*)out, n4);
}

// round 3
// speedup vs baseline: 1.4031x; 1.4031x over previous
#include <cuda_runtime.h>

// Precomputed broadcast row: row[c] = sum_d v[d]*Wo[d,c] + bo[c]
// Derivation: layer_norm over the size-1 kv feature axis returns exactly
// ln_k_b (mu=x, var=0), so k and v are identical for every L position;
// softmax over identical scores is uniform; o = mean_l(v) = v for every query.
// Hence out = msa + (v @ Wo + bo) broadcast over all 16384 rows. Exact.
__device__ float g_row[256];

// Kernel 1: 64 blocks x 256 threads. Block b computes row[4b..4b+4).
// Thread t loads v[t] contribution: float4 Wo[t][4b..4b+3], then smem tree
// reduction over the 256 threads.
__global__ void compute_row_kernel(const float* __restrict__ ln_k_b,
                                   const float* __restrict__ Wv,   // [1,256]
                                   const float* __restrict__ bv,   // [256]
                                   const float* __restrict__ Wo,   // [256,256]
                                   const float* __restrict__ bo)   // [256]
{
    __shared__ float4 part[256];
    int t = threadIdx.x;
    int c4 = blockIdx.x;               // float4 channel group: channels 4*c4..4*c4+3
    float kb = ln_k_b[0];
    float vd = fmaf(kb, Wv[t], bv[t]); // v[d=t], exact kv_x == ln_k_b

    // Wo row d=t, 4 consecutive channels
    float4 w = reinterpret_cast<const float4*>(Wo)[t * 64 + c4];
    float4 p;
    p.x = vd * w.x; p.y = vd * w.y; p.z = vd * w.z; p.w = vd * w.w;
    part[t] = p;
    __syncthreads();

    // tree reduce 256 -> 1
    #pragma unroll
    for (int s = 128; s >= 1; s >>= 1) {
        if (t < s) {
            float4 a = part[t], b = part[t + s];
            a.x += b.x; a.y += b.y; a.z += b.z; a.w += b.w;
            part[t] = a;
        }
        __syncthreads();
    }
    if (t == 0) {
        float4 r = part[0];
        const float4* bo4 = reinterpret_cast<const float4*>(bo);
        float4 b4 = bo4[c4];
        r.x += b4.x; r.y += b4.y; r.z += b4.z; r.w += b4.w;
        reinterpret_cast<float4*>(g_row)[c4] = r;
    }
}

// Kernel 2: out = msa + broadcast(row). 4 float4 per thread, loads batched
// up front for MLP=4. Block covers a contiguous 4096-float4 chunk.
__global__ void add_row_kernel(const float4* __restrict__ msa4,
                               float4* __restrict__ out4,
                               int n4)
{
    int t = threadIdx.x;
    // (element index) mod 64 == t mod 64 for all 4 elements (stride 256)
    float4 r = reinterpret_cast<const float4*>(g_row)[t & 63];

    int base = blockIdx.x * (256 * 4) + t;
    float4 m0, m1, m2, m3;
    bool full = (base + 3 * 256) < n4;
    if (full) {
        m0 = msa4[base];
        m1 = msa4[base + 256];
        m2 = msa4[base + 512];
        m3 = msa4[base + 768];
        m0.x += r.x; m0.y += r.y; m0.z += r.z; m0.w += r.w;
        m1.x += r.x; m1.y += r.y; m1.z += r.z; m1.w += r.w;
        m2.x += r.x; m2.y += r.y; m2.z += r.z; m2.w += r.w;
        m3.x += r.x; m3.y += r.y; m3.z += r.z; m3.w += r.w;
        out4[base]       = m0;
        out4[base + 256] = m1;
        out4[base + 512] = m2;
        out4[base + 768] = m3;
    } else {
        #pragma unroll
        for (int k = 0; k < 4; ++k) {
            int i = base + k * 256;
            if (i < n4) {
                float4 m = msa4[i];
                m.x += r.x; m.y += r.y; m.z += r.z; m.w += r.w;
                out4[i] = m;
            }
        }
    }
}

extern "C" void kernel_launch(void* const* d_in, const int* in_sizes, int n_in,
                              void* d_out, int out_size)
{
    // metadata order: 0 msa, 1 saxs, 2 ln_q_w, 3 ln_q_b, 4 ln_k_w, 5 ln_k_b,
    //                 6 Wq, 7 bq, 8 Wk, 9 bk, 10 Wv, 11 bv, 12 Wo, 13 bo
    const float* msa    = (const float*)d_in[0];
    const float* ln_k_b = (const float*)d_in[5];
    const float* Wv     = (const float*)d_in[10];
    const float* bv     = (const float*)d_in[11];
    const float* Wo     = (const float*)d_in[12];
    const float* bo     = (const float*)d_in[13];
    float* out = (float*)d_out;

    compute_row_kernel<<<64, 256>>>(ln_k_b, Wv, bv, Wo, bo);

    int n4 = out_size / 4;                  // 1,048,576 float4
    int blocks = (n4 + 1023) / 1024;        // 1024 blocks, 4 float4/thread
    add_row_kernel<<<blocks, 256>>>((const float4*)msa, (float4*)out, n4);
}